// round 14
// baseline (speedup 1.0000x reference)
#include <cuda_runtime.h>
#include <cstdint>

// RVQ: x[B,S,768] f32, codebook[3,16,256] f32, alpha scalar.
// Per token, per head: argmax_c (x·k_c - 0.5||k_c||^2)  (== argmin sq-dist)
// out = alpha*x + (1-alpha)*k[best]; code = b0 + 16*b1 + 256*b2 (as f32).
//
// f32x2-packed scheme: smem codebook stores code-pairs {k[c][d], k[c+8][d]}
// per u64, transposed so lane L's chunk reads are conflict-free. Dot FMAs
// run on the packed fma.rn.f32x2 pipe (2 codes per instruction).

typedef unsigned long long u64;

#define NH 3
#define NC 16
#define DHD 256
#define DFULL 768
#define TPW 3
#define NWARPS 4
#define TPB (TPW * NWARPS)   // 12 tokens per block tile
#define FULLMASK 0xffffffffu

__device__ __forceinline__ u64 f2fma(u64 a, u64 b, u64 c) {
    u64 d; asm("fma.rn.f32x2 %0,%1,%2,%3;" : "=l"(d) : "l"(a), "l"(b), "l"(c));
    return d;
}
__device__ __forceinline__ u64 f2add(u64 a, u64 b) {
    u64 d; asm("add.rn.f32x2 %0,%1,%2;" : "=l"(d) : "l"(a), "l"(b));
    return d;
}
__device__ __forceinline__ u64 bcast2(float x) {
    u64 d; unsigned b = __float_as_uint(x);
    asm("mov.b64 %0,{%1,%1};" : "=l"(d) : "r"(b));
    return d;
}
__device__ __forceinline__ float2 unpk(u64 d) {
    unsigned lo, hi;
    asm("mov.b64 {%0,%1},%2;" : "=r"(lo), "=r"(hi) : "l"(d));
    return make_float2(__uint_as_float(lo), __uint_as_float(hi));
}
__device__ __forceinline__ unsigned fmono(float f) {
    int b = __float_as_int(f);
    return (unsigned)(b ^ ((b >> 31) | 0x80000000));
}

// Split-exchange reduce of 8 packed accumulators over 32 lanes.
// Returns the u64 {score(cp), score(cp+8)} where cp = lane bits {4,3,2}.
__device__ __forceinline__ u64 reduce_pairs(u64 a0, u64 a1, u64 a2, u64 a3,
                                            u64 a4, u64 a5, u64 a6, u64 a7,
                                            int lane)
{
    u64 v4[4];
    {
        const bool up = (lane & 16) != 0;
        u64 in0[4] = {a0, a1, a2, a3};
        u64 in1[4] = {a4, a5, a6, a7};
        #pragma unroll
        for (int j = 0; j < 4; j++) {
            u64 snd = up ? in0[j] : in1[j];
            u64 kp  = up ? in1[j] : in0[j];
            v4[j] = f2add(kp, __shfl_xor_sync(FULLMASK, snd, 16));
        }
    }
    u64 v2[2];
    {
        const bool up = (lane & 8) != 0;
        #pragma unroll
        for (int j = 0; j < 2; j++) {
            u64 snd = up ? v4[j]     : v4[j + 2];
            u64 kp  = up ? v4[j + 2] : v4[j];
            v2[j] = f2add(kp, __shfl_xor_sync(FULLMASK, snd, 8));
        }
    }
    u64 w;
    {
        const bool up = (lane & 4) != 0;
        u64 snd = up ? v2[0] : v2[1];
        u64 kp  = up ? v2[1] : v2[0];
        w = f2add(kp, __shfl_xor_sync(FULLMASK, snd, 4));
    }
    w = f2add(w, __shfl_xor_sync(FULLMASK, w, 2));
    w = f2add(w, __shfl_xor_sync(FULLMASK, w, 1));
    return w;
}

__global__ void __launch_bounds__(128, 4) rvq_kernel(
    const float* __restrict__ x,
    const float* __restrict__ cb,
    const float* __restrict__ alphap,
    float* __restrict__ out,
    float* __restrict__ code_out,
    int tokens, int write_code, int ntiles)
{
    // Paired codebook: u64 {k[h][cp][d], k[h][cp+8][d]}.
    // ulonglong2 unit index: h*1024 + cp*128 + i*32 + L  (i = chunk, L = lane)
    // holds dims {8L+2i, 8L+2i+1}. Per 8-lane phase: bank-group = L mod 8,
    // conflict-free for LDS.128.
    __shared__ u64 scb2[NH * 8 * 256];   // 48 KB

    const int tid = threadIdx.x;
    {
        float* sf = (float*)scb2;
        #pragma unroll 4
        for (int g = tid; g < NH * NC * DHD; g += 128) {
            int h = g >> 12, c = (g >> 8) & 15, d = g & 255;
            int cp = c & 7, half = c >> 3;
            int L = d >> 3, i = (d >> 1) & 3, par = d & 1;
            int uidx = (h * 8 + cp) * 256 + (i * 32 + L) * 2 + par;
            sf[2 * uidx + half] = cb[g];
        }
    }
    __syncthreads();

    const int lane = tid & 31;
    const int warp = tid >> 5;
    // code pair owned by this lane after reduction: (cp, cp+8)
    const int cp_own = (((lane >> 4) & 1) << 2) | (((lane >> 3) & 1) << 1)
                     | ((lane >> 2) & 1);

    // One-time half-norms of codes (cp_own, cp_own+8) per head via the same
    // packed pipeline (guarantees layout consistency).
    float hnl[NH], hnh[NH];
    #pragma unroll
    for (int h = 0; h < NH; h++) {
        const ulonglong2* kb = (const ulonglong2*)scb2 + h * 1024 + lane;
        u64 n[8];
        #pragma unroll
        for (int c = 0; c < 8; c++) n[c] = 0ull;
        #pragma unroll
        for (int i = 0; i < 4; i++)
            #pragma unroll
            for (int c = 0; c < 8; c++) {
                ulonglong2 kp = kb[c * 128 + i * 32];
                n[c] = f2fma(kp.x, kp.x, n[c]);
                n[c] = f2fma(kp.y, kp.y, n[c]);
            }
        u64 w = reduce_pairs(n[0], n[1], n[2], n[3], n[4], n[5], n[6], n[7], lane);
        float2 p = unpk(w);
        hnl[h] = 0.5f * p.x;
        hnh[h] = 0.5f * p.y;
    }

    const float alpha = *alphap;
    const float beta  = 1.0f - alpha;

    for (int tile = blockIdx.x; tile < ntiles; tile += gridDim.x) {
        int t0 = tile * TPB + warp * TPW;
        if (t0 > tokens - TPW) t0 = tokens - TPW;   // overlap tail: same values
        if (t0 < 0) t0 = 0;

        int pack[TPW];
        #pragma unroll
        for (int t = 0; t < TPW; t++) pack[t] = 0;

        #pragma unroll
        for (int h = 0; h < NH; h++) {
            // Front-batched x: lane holds dims 8L..8L+7 of head h.
            float4 xa[TPW], xb[TPW];
            const float4* xp0 = (const float4*)(x + t0 * DFULL + h * DHD)
                                + (lane << 1);
            #pragma unroll
            for (int t = 0; t < TPW; t++) {
                xa[t] = xp0[t * 192];
                xb[t] = xp0[t * 192 + 1];
            }

            u64 acc[TPW][8];
            #pragma unroll
            for (int t = 0; t < TPW; t++)
                #pragma unroll
                for (int c = 0; c < 8; c++) acc[t][c] = 0ull;

            const ulonglong2* kb = (const ulonglong2*)scb2 + h * 1024 + lane;

            #pragma unroll
            for (int i = 0; i < 4; i++) {
                u64 xx0[TPW], xx1[TPW];
                #pragma unroll
                for (int t = 0; t < TPW; t++) {
                    float e0, e1;
                    if      (i == 0) { e0 = xa[t].x; e1 = xa[t].y; }
                    else if (i == 1) { e0 = xa[t].z; e1 = xa[t].w; }
                    else if (i == 2) { e0 = xb[t].x; e1 = xb[t].y; }
                    else             { e0 = xb[t].z; e1 = xb[t].w; }
                    xx0[t] = bcast2(e0);
                    xx1[t] = bcast2(e1);
                }
                #pragma unroll
                for (int c = 0; c < 8; c++) {
                    ulonglong2 kp = kb[c * 128 + i * 32];
                    #pragma unroll
                    for (int t = 0; t < TPW; t++) {
                        acc[t][c] = f2fma(xx0[t], kp.x, acc[t][c]);
                        acc[t][c] = f2fma(xx1[t], kp.y, acc[t][c]);
                    }
                }
            }

            #pragma unroll
            for (int t = 0; t < TPW; t++) {
                u64 w = reduce_pairs(acc[t][0], acc[t][1], acc[t][2], acc[t][3],
                                     acc[t][4], acc[t][5], acc[t][6], acc[t][7],
                                     lane);
                float2 p = unpk(w);
                float scl = p.x - hnl[h];
                float sch = p.y - hnh[h];
                unsigned ul = fmono(scl);
                unsigned uh = fmono(sch);
                unsigned ub  = (uh > ul) ? uh : ul;
                unsigned idx = (uh > ul) ? (unsigned)(cp_own + 8)
                                         : (unsigned)cp_own;
                unsigned umax = __reduce_max_sync(FULLMASK, ub);
                unsigned cand = (ub == umax) ? idx : 64u;
                int bi = (int)__reduce_min_sync(FULLMASK, cand);
                pack[t] += bi << (4 * h);

                // Blend: read paired rows, select half by bi>=8.
                const int cpb = bi & 7;
                const bool hiSel = bi >= 8;
                const ulonglong2* kr = (const ulonglong2*)scb2
                                       + h * 1024 + cpb * 128 + lane;
                float kv[8];
                #pragma unroll
                for (int i = 0; i < 4; i++) {
                    ulonglong2 kp = kr[i * 32];
                    float2 p0 = unpk(kp.x);
                    float2 p1 = unpk(kp.y);
                    kv[2 * i]     = hiSel ? p0.y : p0.x;
                    kv[2 * i + 1] = hiSel ? p1.y : p1.x;
                }
                float4 oa, ob;
                oa.x = fmaf(alpha, xa[t].x, beta * kv[0]);
                oa.y = fmaf(alpha, xa[t].y, beta * kv[1]);
                oa.z = fmaf(alpha, xa[t].z, beta * kv[2]);
                oa.w = fmaf(alpha, xa[t].w, beta * kv[3]);
                ob.x = fmaf(alpha, xb[t].x, beta * kv[4]);
                ob.y = fmaf(alpha, xb[t].y, beta * kv[5]);
                ob.z = fmaf(alpha, xb[t].z, beta * kv[6]);
                ob.w = fmaf(alpha, xb[t].w, beta * kv[7]);
                float4* op = (float4*)(out + (t0 + t) * DFULL + h * DHD)
                             + (lane << 1);
                op[0] = oa;
                op[1] = ob;
            }
        }

        if (write_code && lane == 0) {
            #pragma unroll
            for (int t = 0; t < TPW; t++)
                code_out[t0 + t] = (float)pack[t];
        }
    }
}

extern "C" void kernel_launch(void* const* d_in, const int* in_sizes, int n_in,
                              void* d_out, int out_size)
{
    const float* x      = (const float*)d_in[0];
    const float* kernel = (const float*)d_in[1];
    const float* alpha  = (const float*)d_in[2];
    float* out = (float*)d_out;

    const int tokens = in_sizes[0] / DFULL;        // B*S
    const int ntiles = (tokens + TPB - 1) / TPB;

    const long long out_elems = (long long)tokens * DFULL;
    int write_code = (out_size >= out_elems + tokens) ? 1 : 0;
    float* code_out = out + out_elems;

    int grid = ntiles < 592 ? ntiles : 592;   // 4 resident blocks/SM * 148
    rvq_kernel<<<grid, 128>>>(x, kernel, alpha, out, code_out,
                              tokens, write_code, ntiles);
}

// round 16
// speedup vs baseline: 1.1765x; 1.1765x over previous
#include <cuda_runtime.h>
#include <cstdint>

// RVQ: x[B,S,768] f32, codebook[3,16,256] f32, alpha scalar.
// Per token, per head: argmax_c (x·k_c - 0.5||k_c||^2)  (== argmin sq-dist)
// out = alpha*x + (1-alpha)*k[best]; code = b0 + 16*b1 + 256*b2 (as f32).
//
// Head-specialized blocks: each block serves ONE head -> 16KB smem codebook
// -> 5 blocks/SM (20 warps) vs the 4-block ceiling at 48KB. Packed code
// assembled across head-blocks via exact float atomicAdd into a pre-zeroed
// region (ints < 4096: float adds exact & order-independent). Per-token
// guards (no clamp) so each (head, token) contributes exactly once.

#define NH   3
#define NC   16
#define DHD  256
#define DFULL 768
#define NF4  64             // float4 per code row
#define TPW  3              // tokens per warp
#define NWARPS 4
#define TPB  (TPW * NWARPS) // 12 tokens per block tile
#define FULLMASK 0xffffffffu

__device__ __forceinline__ int swz(int j) { return j ^ (j >> 3); }

__device__ __forceinline__ unsigned fmono(float f) {
    int b = __float_as_int(f);
    return (unsigned)(b ^ ((b >> 31) | 0x80000000));
}

__global__ void zero_code_kernel(float* __restrict__ p, int n) {
    int i = blockIdx.x * blockDim.x + threadIdx.x;
    if (i < n) p[i] = 0.f;
}

__global__ void __launch_bounds__(128, 5) rvq_head_kernel(
    const float* __restrict__ x,
    const float* __restrict__ cb,
    const float* __restrict__ alphap,
    float* __restrict__ out,
    float* __restrict__ code_out,
    int tokens, int write_code, int ntiles)
{
    // One head's codebook, XOR-swizzled: lane L reads swz(2L), swz(2L+1)
    // conflict-free per 8-lane phase.
    __shared__ float4 scb[NC * NF4];   // 16 KB

    const int head = blockIdx.x % NH;          // this block's head
    const int tid  = threadIdx.x;
    {
        const float4* cbg = (const float4*)cb + head * NC * NF4;
        #pragma unroll
        for (int g = tid; g < NC * NF4; g += 128) {
            int r = g >> 6, j = g & 63;
            scb[(r << 6) + swz(j)] = cbg[g];
        }
    }
    __syncthreads();

    const int lane = tid & 31;
    const int warp = tid >> 5;
    const int cm   = (lane >> 1) & 15;     // code this lane owns after reduce
    const int sA   = swz(2 * lane);        // lane-constant swizzled offsets
    const int sB   = swz(2 * lane + 1);

    // Half squared norm of code cm (one-time).
    float hn;
    {
        const float4* row = &scb[cm << 6];
        float s = 0.f;
        #pragma unroll
        for (int j = 0; j < NF4; j++) {
            float4 k = row[swz((j + 4 * cm) & 63)];
            s = fmaf(k.x, k.x, s); s = fmaf(k.y, k.y, s);
            s = fmaf(k.z, k.z, s); s = fmaf(k.w, k.w, s);
        }
        hn = 0.5f * s;
    }

    const float alpha = *alphap;
    const float beta  = 1.0f - alpha;
    const int shift   = 4 * head;

    // Blocks with bid % NH == head share this head's tile space.
    const int nblk_h = (gridDim.x - head + NH - 1) / NH;

    for (int tile = blockIdx.x / NH; tile < ntiles; tile += nblk_h) {
        const int t0 = tile * TPB + warp * TPW;

        // Front-batched x (guarded): lane holds 8 contiguous dims.
        float4 xa[TPW], xb[TPW];
        const float4* xp0 = (const float4*)(x + (size_t)t0 * DFULL + head * DHD)
                            + (lane << 1);
        #pragma unroll
        for (int t = 0; t < TPW; t++) {
            if (t0 + t < tokens) {
                xa[t] = xp0[t * 192];
                xb[t] = xp0[t * 192 + 1];
            } else {
                xa[t] = make_float4(0.f, 0.f, 0.f, 0.f);
                xb[t] = xa[t];
            }
        }

        float acc[TPW][NC];
        #pragma unroll
        for (int t = 0; t < TPW; t++)
            #pragma unroll
            for (int c = 0; c < NC; c++) acc[t][c] = 0.f;

        #pragma unroll
        for (int c = 0; c < NC; c++) {
            float4 ka = scb[(c << 6) + sA];
            float4 kb = scb[(c << 6) + sB];
            #pragma unroll
            for (int t = 0; t < TPW; t++) {
                float a = acc[t][c];
                a = fmaf(xa[t].x, ka.x, a);
                a = fmaf(xa[t].y, ka.y, a);
                a = fmaf(xa[t].z, ka.z, a);
                a = fmaf(xa[t].w, ka.w, a);
                a = fmaf(xb[t].x, kb.x, a);
                a = fmaf(xb[t].y, kb.y, a);
                a = fmaf(xb[t].z, kb.z, a);
                a = fmaf(xb[t].w, kb.w, a);
                acc[t][c] = a;
            }
        }

        // Per token: 16-value split-exchange (16 shfl) + REDUX argmax,
        // blend + store, code nibble via atomicAdd (guarded -> exactly once).
        #pragma unroll
        for (int t = 0; t < TPW; t++) {
            float w8[8];
            {
                const bool up = (lane & 16) != 0;
                #pragma unroll
                for (int j = 0; j < 8; j++) {
                    float snd = up ? acc[t][j]     : acc[t][j + 8];
                    float kp  = up ? acc[t][j + 8] : acc[t][j];
                    w8[j] = kp + __shfl_xor_sync(FULLMASK, snd, 16);
                }
            }
            float w4[4];
            {
                const bool up = (lane & 8) != 0;
                #pragma unroll
                for (int j = 0; j < 4; j++) {
                    float snd = up ? w8[j]     : w8[j + 4];
                    float kp  = up ? w8[j + 4] : w8[j];
                    w4[j] = kp + __shfl_xor_sync(FULLMASK, snd, 8);
                }
            }
            float w2[2];
            {
                const bool up = (lane & 4) != 0;
                #pragma unroll
                for (int j = 0; j < 2; j++) {
                    float snd = up ? w4[j]     : w4[j + 2];
                    float kp  = up ? w4[j + 2] : w4[j];
                    w2[j] = kp + __shfl_xor_sync(FULLMASK, snd, 4);
                }
            }
            float w1;
            {
                const bool up = (lane & 2) != 0;
                float snd = up ? w2[0] : w2[1];
                float kp  = up ? w2[1] : w2[0];
                w1 = kp + __shfl_xor_sync(FULLMASK, snd, 2);
            }
            w1 += __shfl_xor_sync(FULLMASK, w1, 1);

            float sc = w1 - hn;      // lane holds score of code cm
            unsigned u = fmono(sc);
            unsigned umax = __reduce_max_sync(FULLMASK, u);
            unsigned cand = (u == umax) ? (unsigned)cm : 64u;
            int bi = (int)__reduce_min_sync(FULLMASK, cand);

            if (t0 + t < tokens) {
                const float4* row = &scb[bi << 6];
                float4 ka = row[sA];
                float4 kb = row[sB];
                float4 oa, ob;
                oa.x = fmaf(alpha, xa[t].x, beta * ka.x);
                oa.y = fmaf(alpha, xa[t].y, beta * ka.y);
                oa.z = fmaf(alpha, xa[t].z, beta * ka.z);
                oa.w = fmaf(alpha, xa[t].w, beta * ka.w);
                ob.x = fmaf(alpha, xb[t].x, beta * kb.x);
                ob.y = fmaf(alpha, xb[t].y, beta * kb.y);
                ob.z = fmaf(alpha, xb[t].z, beta * kb.z);
                ob.w = fmaf(alpha, xb[t].w, beta * kb.w);
                float4* op = (float4*)(out + (size_t)(t0 + t) * DFULL
                                       + head * DHD) + (lane << 1);
                op[0] = oa;
                op[1] = ob;

                if (write_code && lane == 0)
                    atomicAdd(&code_out[t0 + t], (float)(bi << shift));
            }
        }
    }
}

extern "C" void kernel_launch(void* const* d_in, const int* in_sizes, int n_in,
                              void* d_out, int out_size)
{
    const float* x      = (const float*)d_in[0];
    const float* kernel = (const float*)d_in[1];
    const float* alpha  = (const float*)d_in[2];
    float* out = (float*)d_out;

    const int tokens = in_sizes[0] / DFULL;        // B*S
    const int ntiles = (tokens + TPB - 1) / TPB;   // tiles per head

    const long long out_elems = (long long)tokens * DFULL;
    int write_code = (out_size >= out_elems + tokens) ? 1 : 0;
    float* code_out = out + out_elems;

    if (write_code)
        zero_code_kernel<<<(tokens + 255) / 256, 256>>>(code_out, tokens);

    // 5 resident blocks/SM * 148 SMs = 740: one full persistent wave.
    int grid = 740;
    int maxg = ntiles * NH;
    if (grid > maxg) grid = maxg;
    rvq_head_kernel<<<grid, 128>>>(x, kernel, alpha, out, code_out,
                                   tokens, write_code, ntiles);
}

// round 17
// speedup vs baseline: 1.2513x; 1.0636x over previous
#include <cuda_runtime.h>
#include <cstdint>

// RVQ: x[B,S,768] f32, codebook[3,16,256] f32, alpha scalar.
// Per token, per head: argmax_c (x·k_c - 0.5||k_c||^2)  (== argmin sq-dist)
// out = alpha*x + (1-alpha)*k[best]; code = b0 + 16*b1 + 256*b2 (as f32).
//
// Head-specialized blocks (16KB smem codebook -> 5 blocks/SM, 20 warps).
// TPW=4 with codes in 2 groups of 8 (acc[4][8]) to stay within the
// 102-reg/5-block budget while amortizing codebook LDS over 4 tokens.
// Packed code assembled via exact float atomicAdd into a memset-zeroed
// region (ints < 4096: float adds exact & order-independent).

#define NH   3
#define NC   16
#define DHD  256
#define DFULL 768
#define NF4  64             // float4 per code row
#define TPW  4              // tokens per warp
#define NWARPS 4
#define TPB  (TPW * NWARPS) // 16 tokens per block tile
#define FULLMASK 0xffffffffu

__device__ __forceinline__ int swz(int j) { return j ^ (j >> 3); }

__device__ __forceinline__ unsigned fmono(float f) {
    int b = __float_as_int(f);
    return (unsigned)(b ^ ((b >> 31) | 0x80000000));
}

__global__ void __launch_bounds__(128, 5) rvq_head_kernel(
    const float* __restrict__ x,
    const float* __restrict__ cb,
    const float* __restrict__ alphap,
    float* __restrict__ out,
    float* __restrict__ code_out,
    int tokens, int write_code, int ntiles)
{
    // One head's codebook, XOR-swizzled: lane L reads swz(2L), swz(2L+1)
    // conflict-free per 8-lane phase.
    __shared__ float4 scb[NC * NF4];   // 16 KB

    const int head = blockIdx.x % NH;
    const int tid  = threadIdx.x;
    {
        const float4* cbg = (const float4*)cb + head * NC * NF4;
        #pragma unroll
        for (int g = tid; g < NC * NF4; g += 128) {
            int r = g >> 6, j = g & 63;
            scb[(r << 6) + swz(j)] = cbg[g];
        }
    }
    __syncthreads();

    const int lane = tid & 31;
    const int warp = tid >> 5;
    // code owned by this lane (per group) after reduce over lane bits {4,3,2}
    const int lcode = (((lane >> 4) & 1) << 2) | (((lane >> 3) & 1) << 1)
                    | ((lane >> 2) & 1);
    const int sA = swz(2 * lane);
    const int sB = swz(2 * lane + 1);

    // Half squared norms of codes lcode and lcode+8 (one-time).
    float hn0, hn1;
    #pragma unroll
    for (int g = 0; g < 2; g++) {
        const int c = g * 8 + lcode;
        const float4* row = &scb[c << 6];
        float s = 0.f;
        #pragma unroll
        for (int j = 0; j < NF4; j++) {
            float4 k = row[swz((j + 4 * c) & 63)];
            s = fmaf(k.x, k.x, s); s = fmaf(k.y, k.y, s);
            s = fmaf(k.z, k.z, s); s = fmaf(k.w, k.w, s);
        }
        if (g == 0) hn0 = 0.5f * s; else hn1 = 0.5f * s;
    }

    const float alpha = *alphap;
    const float beta  = 1.0f - alpha;
    const int shift   = 4 * head;

    const int nblk_h = (gridDim.x - head + NH - 1) / NH;

    for (int tile = blockIdx.x / NH; tile < ntiles; tile += nblk_h) {
        const int t0 = tile * TPB + warp * TPW;

        // Front-batched x (guarded): lane holds 8 contiguous dims.
        float4 xa[TPW], xb[TPW];
        const float4* xp0 = (const float4*)(x + (size_t)t0 * DFULL + head * DHD)
                            + (lane << 1);
        #pragma unroll
        for (int t = 0; t < TPW; t++) {
            if (t0 + t < tokens) {
                xa[t] = xp0[t * 192];
                xb[t] = xp0[t * 192 + 1];
            } else {
                xa[t] = make_float4(0.f, 0.f, 0.f, 0.f);
                xb[t] = xa[t];
            }
        }

        float sc0[TPW], sc1[TPW];   // per-lane reduced scores, groups 0/1

        #pragma unroll
        for (int g = 0; g < 2; g++) {
            float acc[TPW][8];
            #pragma unroll
            for (int t = 0; t < TPW; t++)
                #pragma unroll
                for (int c = 0; c < 8; c++) acc[t][c] = 0.f;

            #pragma unroll
            for (int c = 0; c < 8; c++) {
                const float4* row = &scb[(g * 8 + c) << 6];
                float4 ka = row[sA];
                float4 kb = row[sB];
                #pragma unroll
                for (int t = 0; t < TPW; t++) {
                    float a = acc[t][c];
                    a = fmaf(xa[t].x, ka.x, a);
                    a = fmaf(xa[t].y, ka.y, a);
                    a = fmaf(xa[t].z, ka.z, a);
                    a = fmaf(xa[t].w, ka.w, a);
                    a = fmaf(xb[t].x, kb.x, a);
                    a = fmaf(xb[t].y, kb.y, a);
                    a = fmaf(xb[t].z, kb.z, a);
                    a = fmaf(xb[t].w, kb.w, a);
                    acc[t][c] = a;
                }
            }

            // 3-stage split-exchange over lane bits {4,3,2} + 2 closing adds.
            #pragma unroll
            for (int t = 0; t < TPW; t++) {
                float w4[4];
                {
                    const bool up = (lane & 16) != 0;
                    #pragma unroll
                    for (int j = 0; j < 4; j++) {
                        float snd = up ? acc[t][j]     : acc[t][j + 4];
                        float kp  = up ? acc[t][j + 4] : acc[t][j];
                        w4[j] = kp + __shfl_xor_sync(FULLMASK, snd, 16);
                    }
                }
                float w2[2];
                {
                    const bool up = (lane & 8) != 0;
                    #pragma unroll
                    for (int j = 0; j < 2; j++) {
                        float snd = up ? w4[j]     : w4[j + 2];
                        float kp  = up ? w4[j + 2] : w4[j];
                        w2[j] = kp + __shfl_xor_sync(FULLMASK, snd, 8);
                    }
                }
                float w1;
                {
                    const bool up = (lane & 4) != 0;
                    float snd = up ? w2[0] : w2[1];
                    float kp  = up ? w2[1] : w2[0];
                    w1 = kp + __shfl_xor_sync(FULLMASK, snd, 4);
                }
                w1 += __shfl_xor_sync(FULLMASK, w1, 2);
                w1 += __shfl_xor_sync(FULLMASK, w1, 1);
                if (g == 0) sc0[t] = w1 - hn0;
                else        sc1[t] = w1 - hn1;
            }
        }

        // Argmax over 16 codes (local pair best + REDUX), blend, store.
        #pragma unroll
        for (int t = 0; t < TPW; t++) {
            unsigned u0 = fmono(sc0[t]);
            unsigned u1 = fmono(sc1[t]);
            unsigned ub  = (u1 > u0) ? u1 : u0;
            unsigned idx = (u1 > u0) ? (unsigned)(lcode + 8)
                                     : (unsigned)lcode;
            unsigned umax = __reduce_max_sync(FULLMASK, ub);
            unsigned cand = (ub == umax) ? idx : 64u;
            int bi = (int)__reduce_min_sync(FULLMASK, cand);

            if (t0 + t < tokens) {
                const float4* row = &scb[bi << 6];
                float4 ka = row[sA];
                float4 kb = row[sB];
                float4 oa, ob;
                oa.x = fmaf(alpha, xa[t].x, beta * ka.x);
                oa.y = fmaf(alpha, xa[t].y, beta * ka.y);
                oa.z = fmaf(alpha, xa[t].z, beta * ka.z);
                oa.w = fmaf(alpha, xa[t].w, beta * ka.w);
                ob.x = fmaf(alpha, xb[t].x, beta * kb.x);
                ob.y = fmaf(alpha, xb[t].y, beta * kb.y);
                ob.z = fmaf(alpha, xb[t].z, beta * kb.z);
                ob.w = fmaf(alpha, xb[t].w, beta * kb.w);
                float4* op = (float4*)(out + (size_t)(t0 + t) * DFULL
                                       + head * DHD) + (lane << 1);
                op[0] = oa;
                op[1] = ob;

                if (write_code && lane == 0)
                    atomicAdd(&code_out[t0 + t], (float)(bi << shift));
            }
        }
    }
}

extern "C" void kernel_launch(void* const* d_in, const int* in_sizes, int n_in,
                              void* d_out, int out_size)
{
    const float* x      = (const float*)d_in[0];
    const float* kernel = (const float*)d_in[1];
    const float* alpha  = (const float*)d_in[2];
    float* out = (float*)d_out;

    const int tokens = in_sizes[0] / DFULL;        // B*S
    const int ntiles = (tokens + TPB - 1) / TPB;   // tiles per head

    const long long out_elems = (long long)tokens * DFULL;
    int write_code = (out_size >= out_elems + tokens) ? 1 : 0;
    float* code_out = out + out_elems;

    if (write_code)
        cudaMemsetAsync(code_out, 0, (size_t)tokens * sizeof(float));

    // 5 resident blocks/SM * 148 SMs = 740: one full persistent wave.
    int grid = 740;
    int maxg = ntiles * NH;
    if (grid > maxg) grid = maxg;
    rvq_head_kernel<<<grid, 128>>>(x, kernel, alpha, out, code_out,
                                   tokens, write_code, ntiles);
}